// round 15
// baseline (speedup 1.0000x reference)
#include <cuda_runtime.h>
#include <math.h>

// CNO_LReLu: antialiased bicubic upsample x2 (2048->4096), LeakyReLU(0.01),
// antialiased bicubic downsample x2 (4096->2048), per (b,c) row. B*C = 8192 rows.
//
// R13 (resubmission; broker timeout): 8 outputs/thread (TPB 256). Per 8
// outputs: 4 LDG.128 (was 6), 11 stage-1 pairs (was 14), constants amortized
// 2x. LeakyReLU scalar FMNMX on the alu pipe (R12 post-mortem: packed lrelu2
// moved work onto the fma pipe and regressed 11%). Edge index maps re-audited.

#define IN_SIZE  2048
#define OUT_SIZE 2048
#define NROWS    8192
#define TPB      256        // 8 outputs per thread

typedef unsigned long long u64;

__device__ __forceinline__ u64 pack2(float a, float b) {
    u64 r;
    asm("mov.b64 %0, {%1, %2};" : "=l"(r)
        : "r"(__float_as_uint(a)), "r"(__float_as_uint(b)));
    return r;
}
__device__ __forceinline__ void unpack2(u64 v, float& a, float& b) {
    unsigned x, y;
    asm("mov.b64 {%0, %1}, %2;" : "=r"(x), "=r"(y) : "l"(v));
    a = __uint_as_float(x); b = __uint_as_float(y);
}
__device__ __forceinline__ u64 fma2(u64 a, u64 b, u64 c) {
    u64 d;
    asm("fma.rn.f32x2 %0, %1, %2, %3;" : "=l"(d) : "l"(a), "l"(b), "l"(c));
    return d;
}
__device__ __forceinline__ u64 mul2(u64 a, u64 b) {
    u64 d;
    asm("mul.rn.f32x2 %0, %1, %2;" : "=l"(d) : "l"(a), "l"(b));
    return d;
}

// Interior upsample weight vectors (exact Keys-cubic values, sum = 1):
//   odd  mid-index o: taps x[(o-1)/2-1 .. +2],  W_O
//   even mid-index o: taps x[o/2-2    .. +1],  W_E
#define WO4(a,b,c,d) fmaf(-0.0703125f,(a), fmaf(0.8671875f,(b), fmaf(0.2265625f,(c), -0.0234375f*(d))))
#define WE4(a,b,c,d) fmaf(-0.0234375f,(a), fmaf(0.2265625f,(b), fmaf(0.8671875f,(c), -0.0703125f*(d))))

__device__ __forceinline__ float lrelu(float v) {
    return fmaxf(v, 0.01f * v);   // == LeakyReLU(0.01); FMNMX on alu pipe
}

// Scalar stage-2 (edge threads): out = W2 . z[0..7]  (9th tap weight is 0)
__device__ __forceinline__ float stage2(const float* __restrict__ z) {
    float a =  fmaf(-0.01171875f, z[0], -0.03515625f * z[1]);
    a = fmaf( 0.11328125f, z[2], a);
    a = fmaf( 0.43359375f, z[3], a);
    a = fmaf( 0.43359375f, z[4], a);
    a = fmaf( 0.11328125f, z[5], a);
    a = fmaf(-0.03515625f, z[6], a);
    a = fmaf(-0.01171875f, z[7], a);
    return a;
}

__global__ void __launch_bounds__(TPB, 4)
cno_lrelu_kernel(const float* __restrict__ x, float* __restrict__ out) {
    const int row = blockIdx.x;
    const float* __restrict__ xr = x + (size_t)row * IN_SIZE;
    float* __restrict__ orow = out + (size_t)row * OUT_SIZE;

    const int t = threadIdx.x;

    // 16-float window; interior base = 8t-4 covers x[8t-3 .. 8t+10] needed by
    // outputs 8t..8t+7 (mids y[16t-3 .. 16t+18]).
    const int base = (t == 0) ? 0 : ((t == TPB - 1) ? (IN_SIZE - 16) : 8 * t - 4);

    float xv[16];
    #pragma unroll
    for (int q = 0; q < 4; ++q)
        *reinterpret_cast<float4*>(&xv[4 * q]) =
            *reinterpret_cast<const float4*>(&xr[base + 4 * q]);

    float o[8];

    if (t == 0) {
        // ---- Left edge: outputs 0..7, mids z[j]=y[j], j=0..18; y[0..2] special ----
        float z[19];
        z[0] = fmaf(0.8671875f, xv[0], -0.0703125f * xv[1]) * (1.0f / 0.796875f);
        z[1] = fmaf(0.8671875f, xv[0], fmaf(0.2265625f, xv[1], -0.0234375f * xv[2])) * (1.0f / 1.0703125f);
        z[2] = fmaf(0.2265625f, xv[0], fmaf(0.8671875f, xv[1], -0.0703125f * xv[2])) * (1.0f / 1.0234375f);
        #pragma unroll
        for (int m = 3; m <= 18; ++m) {
            const int s = (m - 3) >> 1;
            z[m] = (m & 1) ? WO4(xv[s], xv[s+1], xv[s+2], xv[s+3])
                           : WE4(xv[s], xv[s+1], xv[s+2], xv[s+3]);
        }
        #pragma unroll
        for (int m = 0; m <= 18; ++m) z[m] = lrelu(z[m]);

        o[0] = fmaf(0.8671875f, z[0] + z[1],
               fmaf(0.2265625f, z[2],
               fmaf(-0.0703125f, z[3], -0.0234375f * z[4]))) * (1.0f / 1.8671875f);
        o[1] = (fmaf(-0.0703125f, z[0],
                fmaf( 0.2265625f, z[1],
                fmaf( 0.8671875f, z[2] + z[3],
                fmaf( 0.2265625f, z[4],
                fmaf(-0.0703125f, z[5], -0.0234375f * z[6])))))) * (1.0f / 2.0234375f);
        #pragma unroll
        for (int i = 2; i < 8; ++i) o[i] = stage2(z + (2 * i - 3));
    } else if (t == TPB - 1) {
        // ---- Right edge: outputs 2040..2047, z[j]=y[4077+j], j=0..18 ----
        // base = 2032: xv[i] = x[2032+i]; y[4093..4095] special.
        float z[19];
        #pragma unroll
        for (int j = 0; j <= 15; ++j) {
            const int s = (j >> 1) + 5;   // j=0 -> y[4077] (odd), taps xv[5..8]
            z[j] = (j & 1) ? WE4(xv[s], xv[s+1], xv[s+2], xv[s+3])
                           : WO4(xv[s], xv[s+1], xv[s+2], xv[s+3]);
        }
        z[16] = fmaf(-0.0703125f, xv[13], fmaf(0.8671875f, xv[14], 0.2265625f * xv[15])) * (1.0f / 1.0234375f);
        z[17] = fmaf(-0.0234375f, xv[13], fmaf(0.2265625f, xv[14], 0.8671875f * xv[15])) * (1.0f / 1.0703125f);
        z[18] = fmaf(-0.0703125f, xv[14], 0.8671875f * xv[15]) * (1.0f / 0.796875f);
        #pragma unroll
        for (int m = 0; m <= 18; ++m) z[m] = lrelu(z[m]);

        #pragma unroll
        for (int i = 0; i < 6; ++i) o[i] = stage2(z + 2 * i);   // outs 2040..2045
        o[6] = (fmaf(-0.0703125f, z[18],
                fmaf( 0.2265625f, z[17],
                fmaf( 0.8671875f, z[16] + z[15],
                fmaf( 0.2265625f, z[14],
                fmaf(-0.0703125f, z[13], -0.0234375f * z[12])))))) * (1.0f / 2.0234375f);
        o[7] = fmaf(0.8671875f, z[18] + z[17],
               fmaf(0.2265625f, z[16],
               fmaf(-0.0703125f, z[15], -0.0234375f * z[14]))) * (1.0f / 1.8671875f);
    } else {
        // ---- Interior, f32x2 stage-1/stage-2, scalar FMNMX activation ----
        // Pair k (k=0..10): (y[16t-3+2k], y[16t-2+2k]) both tap xv[k+1..k+4];
        // lane lo = odd-mid weights W_O, lane hi = even-mid weights W_E.
        const u64 WP0 = pack2(-0.0703125f, -0.0234375f);
        const u64 WP1 = pack2( 0.8671875f,  0.2265625f);
        const u64 WP2 = pack2( 0.2265625f,  0.8671875f);
        const u64 WP3 = pack2(-0.0234375f, -0.0703125f);
        // Stage-2 packed weight pairs: (W2[0],W2[1]) .. (W2[6],W2[7])
        const u64 VP0 = pack2(-0.01171875f, -0.03515625f);
        const u64 VP1 = pack2( 0.11328125f,  0.43359375f);
        const u64 VP2 = pack2( 0.43359375f,  0.11328125f);
        const u64 VP3 = pack2(-0.03515625f, -0.01171875f);

        // Broadcast packs of xv[1..14]; xx[j] = (xv[j+1], xv[j+1]).
        u64 xx[14];
        #pragma unroll
        for (int i = 0; i < 14; ++i) xx[i] = pack2(xv[i + 1], xv[i + 1]);

        // Pair k contributes to out[i] for i = k-3..k (weights VP_{k-i}).
        u64 acc[8];
        #pragma unroll
        for (int k = 0; k < 11; ++k) {
            u64 y2 = mul2(WP0, xx[k]);
            y2 = fma2(WP1, xx[k + 1], y2);
            y2 = fma2(WP2, xx[k + 2], y2);
            y2 = fma2(WP3, xx[k + 3], y2);

            float z0, z1;
            unpack2(y2, z0, z1);
            z0 = fmaxf(z0, 0.01f * z0);       // FMNMX on alu pipe (parallel)
            z1 = fmaxf(z1, 0.01f * z1);
            const u64 zz = pack2(z0, z1);

            if (k <= 7)            acc[k]     = mul2(VP0, zz);
            if (k >= 1 && k <= 8)  acc[k - 1] = fma2(VP1, zz, acc[k - 1]);
            if (k >= 2 && k <= 9)  acc[k - 2] = fma2(VP2, zz, acc[k - 2]);
            if (k >= 3)            acc[k - 3] = fma2(VP3, zz, acc[k - 3]);
        }

        #pragma unroll
        for (int i = 0; i < 8; ++i) {
            float a0, a1;
            unpack2(acc[i], a0, a1);
            o[i] = a0 + a1;
        }
    }

    // Two coalesced STG.128 per thread: outputs 8t..8t+7.
    float4 v0 = make_float4(o[0], o[1], o[2], o[3]);
    float4 v1 = make_float4(o[4], o[5], o[6], o[7]);
    reinterpret_cast<float4*>(orow)[2 * t]     = v0;
    reinterpret_cast<float4*>(orow)[2 * t + 1] = v1;
}

extern "C" void kernel_launch(void* const* d_in, const int* in_sizes, int n_in,
                              void* d_out, int out_size) {
    const float* x = (const float*)d_in[0];
    float* out = (float*)d_out;
    cno_lrelu_kernel<<<NROWS, TPB>>>(x, out);
}